// round 15
// baseline (speedup 1.0000x reference)
#include <cuda_runtime.h>
#include <math.h>
#include <stdint.h>

#define BB 8
#define CC 192
#define HH 128
#define WW 128
#define HWW (HH*WW)          // 16384
#define NHEADS 4
#define SS 48
#define NPB (CC*HWW)         // 3145728 per batch per tensor
#define NTOT (BB*NPB)

// ---------------- scratch ----------------
__device__ float g_mu[BB*HWW];          // per-pixel LN mean
__device__ float g_rs[BB*HWW];          // per-pixel LN rsqrt(var+eps)
__device__ uint16_t g_tmp16[3*NTOT];    // pw outputs Qp,Kp,Vp (bf16)
__device__ uint16_t g_vt16[NTOT];       // Vt (spatially transposed V after dw, bf16)
__device__ float g_att[BB*NHEADS*SS*SS];
__device__ float g_Gm[BB*256*CC];       // fused matrix per batch, [b][o(pad 256)][cv]
__device__ float g_w3[640*CC];          // stacked pw weights [m(pad 640)][k], fp32
__device__ uint32_t g_w3f[5*6*2048];    // pre-formatted bf16 A fragments
__device__ float g_b3[3*CC];

__device__ __forceinline__ uint32_t bf2(float lo, float hi) {
    uint32_t d;
    asm("cvt.rn.bf16x2.f32 %0, %1, %2;" : "=r"(d) : "f"(hi), "f"(lo));
    return d;
}
__device__ __forceinline__ float bf_lo(uint32_t u) { return __uint_as_float(u << 16); }
__device__ __forceinline__ float bf_hi(uint32_t u) { return __uint_as_float(u & 0xffff0000u); }

// ---------------- weight prep ----------------
__global__ void prep_weights_kernel(const float* __restrict__ qw, const float* __restrict__ kw,
                                    const float* __restrict__ vw, const float* __restrict__ qb,
                                    const float* __restrict__ kb, const float* __restrict__ vb) {
    int idx = blockIdx.x * 256 + threadIdx.x;
    if (idx < 640 * CC) {
        int m = idx / CC, k = idx % CC;
        float v = 0.0f;
        if (m < 576) {
            int slot = m / CC, o = m % CC;
            const float* w = (slot == 0) ? qw : (slot == 1) ? kw : vw;
            v = w[o * CC + k];
        }
        g_w3[idx] = v;
    }
    if (idx < 3 * CC) {
        int i = idx / CC, o = idx % CC;
        const float* bs = (i == 0) ? qb : (i == 1) ? kb : vb;
        g_b3[idx] = bs[o];
    }
}

// format g_w3 -> bf16 fragment layout. grid (5,6), 256 thr
__global__ void prep_frag_kernel() {
    int mb = blockIdx.x, kc = blockIdx.y;
    int tid = threadIdx.x;
    uint32_t* dst = g_w3f + (mb * 6 + kc) * 2048;
    #pragma unroll
    for (int u = 0; u < 2; u++) {
        int unit = tid + u * 256;
        int koq  = unit & 3;
        int g    = (unit >> 2) & 7;
        int ks   = (unit >> 5) & 1;
        int msub = unit >> 6;
        int r0 = mb * 128 + msub * 16 + g;
        int koff = koq * 4;
        int kk = kc * 32 + ks * 16 + koff;
        float4 v0 = *(const float4*)&g_w3[(size_t)r0 * CC + kk];
        float4 v1 = *(const float4*)&g_w3[(size_t)(r0 + 8) * CC + kk];
        int lane0 = g * 4 + ((koq * 2) & 3);
        int regbase = (koff >= 8) ? 2 : 0;
        uint32_t* blk = dst + (msub * 2 + ks) * 128;
        *(uint2*)(blk + lane0 * 4 + regbase)       = make_uint2(bf2(v0.x, v0.y), bf2(v1.x, v1.y));
        *(uint2*)(blk + (lane0 + 1) * 4 + regbase) = make_uint2(bf2(v0.z, v0.w), bf2(v1.z, v1.w));
    }
}

__global__ void zero_att_kernel() {
    int idx = blockIdx.x * 256 + threadIdx.x;
    if (idx < BB * NHEADS * SS * SS) g_att[idx] = 0.0f;
}

// ---------------- LN stats, 2 threads/pixel ----------------
__global__ __launch_bounds__(256) void ln_stats_kernel(const float* __restrict__ x) {
    __shared__ float ss[128], sq2[128];
    int tid = threadIdx.x;
    int p = blockIdx.x * 128 + (tid >> 1);
    int half = tid & 1;
    int b = p / HWW, sp = p % HWW;
    const float* xp = x + (size_t)b * NPB + sp + (size_t)(half * 96) * HWW;
    float s = 0.f, sq = 0.f;
    #pragma unroll 4
    for (int c = 0; c < 96; c++) {
        float v = xp[(size_t)c * HWW];
        s += v; sq += v * v;
    }
    if (half) { ss[tid >> 1] = s; sq2[tid >> 1] = sq; }
    __syncthreads();
    if (!half) {
        s += ss[tid >> 1]; sq += sq2[tid >> 1];
        float mu = s * (1.0f / CC);
        float var = sq * (1.0f / CC) - mu * mu;
        g_mu[p] = mu;
        g_rs[p] = rsqrtf(var + 1e-5f);
    }
}

// ============== bf16 mma.sync GEMM machinery ==============
#define A_BLK 132
#define B_BLK2 132
#define A_CH (16 * A_BLK)     // 2112 u32
#define B_CH (16 * B_BLK2)    // 2112 u32
#define BUF_U32 (A_CH + B_CH) // 4224
#define SMEM_DB (2 * BUF_U32 * 4)   // 33792 B (final GEMM)
#define STAGE_PITCH 136
#define WORK_U32 8704               // 34816 B: A double-buffer / epilogue stage
#define SMEM_QKV ((6 * B_CH + WORK_U32) * 4)   // 85504 B

#define MMA_BF16(acc, a0, a1, a2, a3, b0, b1) \
    asm volatile( \
        "mma.sync.aligned.m16n8k16.row.col.f32.bf16.bf16.f32 " \
        "{%0,%1,%2,%3}, {%4,%5,%6,%7}, {%8,%9}, {%0,%1,%2,%3};" \
        : "+f"((acc)[0]), "+f"((acc)[1]), "+f"((acc)[2]), "+f"((acc)[3]) \
        : "r"(a0), "r"(a1), "r"(a2), "r"(a3), "r"(b0), "r"(b1))

__device__ __forceinline__ void fill_A_pre(uint32_t* Ab, const uint32_t* src, int tid) {
    #pragma unroll
    for (int u = 0; u < 2; u++) {
        int f = tid + u * 256;
        int blk = f >> 5, lane = f & 31;
        uint4 v = ((const uint4*)src)[f];
        *(uint4*)(Ab + blk * A_BLK + lane * 4) = v;
    }
}

__device__ __forceinline__ void fill_A_f32(uint32_t* Ab, const float* Amat,
                                           int kbase, int arows, int tid) {
    #pragma unroll
    for (int u = 0; u < 2; u++) {
        int unit = tid + u * 256;
        int koq  = unit & 3;
        int g    = (unit >> 2) & 7;
        int ks   = (unit >> 5) & 1;
        int msub = unit >> 6;
        int r0 = msub * 16 + g;
        int koff = koq * 4;
        int kk = kbase + ks * 16 + koff;
        float4 v0 = make_float4(0.f,0.f,0.f,0.f), v1 = v0;
        if (r0 < arows)     v0 = *(const float4*)&Amat[(size_t)r0 * CC + kk];
        if (r0 + 8 < arows) v1 = *(const float4*)&Amat[(size_t)(r0 + 8) * CC + kk];
        int lane0 = g * 4 + ((koq * 2) & 3);
        int regbase = (koff >= 8) ? 2 : 0;
        uint32_t* blk = Ab + (msub * 2 + ks) * A_BLK;
        *(uint2*)(blk + lane0 * 4 + regbase)       = make_uint2(bf2(v0.x, v0.y), bf2(v1.x, v1.y));
        *(uint2*)(blk + (lane0 + 1) * 4 + regbase) = make_uint2(bf2(v0.z, v0.w), bf2(v1.z, v1.w));
    }
}

// ---- QKV B path: fp32 x + LN ----
__device__ __forceinline__ void load_B4(float4 v[4], const float* X,
                                        int kbase, int pix0, int tid) {
    int n4 = (tid & 31) * 4;
    int kp = (tid >> 5) & 3;
    int ks = tid >> 7;
    const float* base = X + (size_t)(kbase + ks * 16) * HWW + pix0 + n4;
    v[0] = *(const float4*)(base + (size_t)(2 * kp) * HWW);
    v[1] = *(const float4*)(base + (size_t)(2 * kp + 1) * HWW);
    v[2] = *(const float4*)(base + (size_t)(2 * kp + 8) * HWW);
    v[3] = *(const float4*)(base + (size_t)(2 * kp + 9) * HWW);
}

__device__ __forceinline__ void store_B_ln(uint32_t* Bb, const float4 v[4], int tid,
                                           const float4 mu4, const float4 r4,
                                           const float* __restrict__ lnw,
                                           const float* __restrict__ lnb, int kbase) {
    int n4 = (tid & 31) * 4;
    int kp = (tid >> 5) & 3;
    int ks = tid >> 7;
    int kk = kbase + ks * 16;
    float lw[4], lb[4];
    lw[0] = lnw[kk + 2*kp];     lb[0] = lnb[kk + 2*kp];
    lw[1] = lnw[kk + 2*kp + 1]; lb[1] = lnb[kk + 2*kp + 1];
    lw[2] = lnw[kk + 2*kp + 8]; lb[2] = lnb[kk + 2*kp + 8];
    lw[3] = lnw[kk + 2*kp + 9]; lb[3] = lnb[kk + 2*kp + 9];
    const float* e0 = (const float*)&v[0];
    const float* e1 = (const float*)&v[1];
    const float* e2 = (const float*)&v[2];
    const float* e3 = (const float*)&v[3];
    const float* mup = (const float*)&mu4;
    const float* rp  = (const float*)&r4;
    #pragma unroll
    for (int q = 0; q < 4; q++) {
        float sc = rp[q], mm = mup[q];
        float f0 = (e0[q] - mm) * sc * lw[0] + lb[0];
        float f1 = (e1[q] - mm) * sc * lw[1] + lb[1];
        float f2 = (e2[q] - mm) * sc * lw[2] + lb[2];
        float f3 = (e3[q] - mm) * sc * lw[3] + lb[3];
        int n = n4 + q;
        int npair = n >> 4, sub = (n >> 3) & 1, lane = (n & 7) * 4 + kp;
        *(uint2*)(Bb + (npair * 2 + ks) * B_BLK2 + lane * 4 + sub * 2) =
            make_uint2(bf2(f0, f1), bf2(f2, f3));
    }
}

// ---- final-GEMM B path: bf16 Vt, pure bit-shuffle ----
__device__ __forceinline__ void load_B4_bf(uint2 v[4], const uint16_t* X16,
                                           int kbase, int pix0, int tid) {
    int n4 = (tid & 31) * 4;
    int kp = (tid >> 5) & 3;
    int ks = tid >> 7;
    const uint16_t* base = X16 + (size_t)(kbase + ks * 16) * HWW + pix0 + n4;
    v[0] = *(const uint2*)(base + (size_t)(2 * kp) * HWW);
    v[1] = *(const uint2*)(base + (size_t)(2 * kp + 1) * HWW);
    v[2] = *(const uint2*)(base + (size_t)(2 * kp + 8) * HWW);
    v[3] = *(const uint2*)(base + (size_t)(2 * kp + 9) * HWW);
}
__device__ __forceinline__ uint32_t bfsel(const uint2 r, int q) {
    uint32_t w = (q < 2) ? r.x : r.y;
    return (q & 1) ? (w >> 16) : (w & 0xffffu);
}
__device__ __forceinline__ void store_B_bf(uint32_t* Bb, const uint2 v[4], int tid) {
    int n4 = (tid & 31) * 4;
    int kp = (tid >> 5) & 3;
    int ks = tid >> 7;
    #pragma unroll
    for (int q = 0; q < 4; q++) {
        uint32_t lo = bfsel(v[0], q) | (bfsel(v[1], q) << 16);
        uint32_t hi = bfsel(v[2], q) | (bfsel(v[3], q) << 16);
        int n = n4 + q;
        int npair = n >> 4, sub = (n >> 3) & 1, lane = (n & 7) * 4 + kp;
        *(uint2*)(Bb + (npair * 2 + ks) * B_BLK2 + lane * 4 + sub * 2) = make_uint2(lo, hi);
    }
}

__device__ __forceinline__ void mma_chunk(float acc[4][4][4], const uint32_t* Ab,
                                          const uint32_t* Bb, int wm, int wnp, int lane) {
    #pragma unroll
    for (int ks = 0; ks < 2; ks++) {
        uint32_t ah[4][4], bh[4][2];
        #pragma unroll
        for (int i = 0; i < 4; i++) {
            uint4 t = *(const uint4*)(Ab + ((wm + i) * 2 + ks) * A_BLK + lane * 4);
            ah[i][0] = t.x; ah[i][1] = t.y; ah[i][2] = t.z; ah[i][3] = t.w;
        }
        #pragma unroll
        for (int jp = 0; jp < 2; jp++) {
            uint4 t = *(const uint4*)(Bb + ((wnp + jp) * 2 + ks) * B_BLK2 + lane * 4);
            bh[jp*2][0] = t.x; bh[jp*2][1] = t.y;
            bh[jp*2+1][0] = t.z; bh[jp*2+1][1] = t.w;
        }
        #pragma unroll
        for (int i = 0; i < 4; i++)
            #pragma unroll
            for (int j = 0; j < 4; j++)
                MMA_BF16(acc[i][j], ah[i][0], ah[i][1], ah[i][2], ah[i][3], bh[j][0], bh[j][1]);
    }
}

// ---------------- QKV GEMM: B-resident, loop all 5 m-blocks in one CTA ----------------
__global__ __launch_bounds__(256, 2) void gemm_qkv_mma_kernel(const float* __restrict__ x,
                                                              const float* __restrict__ lnw,
                                                              const float* __restrict__ lnb) {
    extern __shared__ uint32_t usm[];
    uint32_t* Bres = usm;                 // 6 chunks, LN'd bf16, resident
    uint32_t* work = usm + 6 * B_CH;      // A double-buffer / epilogue stage
    const int tid = threadIdx.x;
    const int wid = tid >> 5, lane = tid & 31;
    const int pix0 = blockIdx.x * 128;
    const int b = blockIdx.y;
    const int wm = (wid & 1) * 4;
    const int wnp = (wid >> 1) * 2;
    const float* X = x + (size_t)b * NPB;

    float4 mu4, r4;
    {
        int n4 = (tid & 31) * 4;
        mu4 = *(const float4*)&g_mu[(size_t)b * HWW + pix0 + n4];
        r4  = *(const float4*)&g_rs[(size_t)b * HWW + pix0 + n4];
    }
    // build all 6 B chunks once
    #pragma unroll 1
    for (int kc = 0; kc < 6; kc++) {
        float4 breg[4];
        load_B4(breg, X, kc * 32, pix0, tid);
        store_B_ln(Bres + kc * B_CH, breg, tid, mu4, r4, lnw, lnb, kc * 32);
    }
    fill_A_pre(work, g_w3f, tid);     // mb0 chunk0 -> buffer 0
    __syncthreads();

    int g = lane >> 2, t = lane & 3;
    #pragma unroll 1
    for (int mb = 0; mb < 5; mb++) {
        const uint32_t* Asrc = g_w3f + mb * 6 * 2048;
        float acc[4][4][4] = {};
        #pragma unroll 1
        for (int kc = 0; kc < 6; kc++) {
            uint32_t* cur = work + (kc & 1) * A_CH;
            uint32_t* nxt = work + ((kc + 1) & 1) * A_CH;
            if (kc < 5) fill_A_pre(nxt, Asrc + (kc + 1) * 2048, tid);
            mma_chunk(acc, cur, Bres + kc * B_CH, wm, wnp, lane);
            __syncthreads();
        }
        // epilogue: stage bf16 tile, then coalesced uint4 stores
        uint16_t* stage = (uint16_t*)work;
        int m0 = mb * 128;
        #pragma unroll
        for (int i = 0; i < 4; i++) {
            #pragma unroll
            for (int half = 0; half < 2; half++) {
                int mrow = (wid & 1) * 64 + i * 16 + g + half * 8;
                int m = m0 + mrow;
                float bias = (m < 576) ? g_b3[m] : 0.f;
                #pragma unroll
                for (int j = 0; j < 4; j++) {
                    int px = (wid >> 1) * 32 + j * 8 + 2 * t;
                    *(uint32_t*)&stage[mrow * STAGE_PITCH + px] =
                        bf2(acc[i][j][half*2+0] + bias, acc[i][j][half*2+1] + bias);
                }
            }
        }
        __syncthreads();
        #pragma unroll
        for (int u = 0; u < 8; u++) {
            int f = tid + u * 256;
            int mrow = f >> 4, chunk = f & 15;
            int m = m0 + mrow;
            if (m >= 576) continue;
            int slot = m / CC, o = m - slot * CC;
            uint4 v = *(const uint4*)&stage[mrow * STAGE_PITCH + chunk * 8];
            *(uint4*)&g_tmp16[(size_t)slot * NTOT + (size_t)b * NPB + (size_t)o * HWW + pix0 + chunk * 8] = v;
        }
        if (mb < 4) {
            __syncthreads();
            fill_A_pre(work, g_w3f + (mb + 1) * 6 * 2048, tid);   // next mb chunk0 -> buffer 0
            __syncthreads();
        }
    }
}

// ---------------- final GEMM: y = G[b] @ Vt(bf16) + f_b + xn(recomputed) ----------------
__global__ __launch_bounds__(256, 2) void gemm_final_mma_kernel(const float* __restrict__ x,
                                                                const float* __restrict__ lnw,
                                                                const float* __restrict__ lnb,
                                                                const float* __restrict__ fb,
                                                                float* __restrict__ out) {
    extern __shared__ uint32_t usm[];
    const int tid = threadIdx.x;
    const int wid = tid >> 5, lane = tid & 31;
    const int m0 = blockIdx.x * 128;
    const int pix0 = blockIdx.y * 128;
    const int b = blockIdx.z;
    const int arows = (m0 == 0) ? 128 : (CC - 128);
    const int wm = (wid & 1) * 4;
    const int wnp = (wid >> 1) * 2;
    const float* Amat = g_Gm + ((size_t)b * 256 + m0) * CC;
    const uint16_t* X16 = g_vt16 + (size_t)b * NPB;

    float acc[4][4][4] = {};
    uint2 breg[4];
    load_B4_bf(breg, X16, 0, pix0, tid);
    fill_A_f32(usm, Amat, 0, arows, tid);
    store_B_bf(usm + A_CH, breg, tid);
    __syncthreads();
    #pragma unroll 1
    for (int kc = 0; kc < 6; kc++) {
        uint32_t* cur = usm + (kc & 1) * BUF_U32;
        uint32_t* nxt = usm + ((kc + 1) & 1) * BUF_U32;
        if (kc < 5) load_B4_bf(breg, X16, (kc + 1) * 32, pix0, tid);
        mma_chunk(acc, cur, cur + A_CH, wm, wnp, lane);
        if (kc < 5) {
            fill_A_f32(nxt, Amat, (kc + 1) * 32, arows, tid);
            store_B_bf(nxt + A_CH, breg, tid);
        }
        __syncthreads();
    }

    int g = lane >> 2, t = lane & 3;
    const float* xb = x + (size_t)b * NPB;
    const float* mup = g_mu + (size_t)b * HWW;
    const float* rsp = g_rs + (size_t)b * HWW;
    float2 m2a[4], r2a[4];
    #pragma unroll
    for (int j = 0; j < 4; j++) {
        int pix = pix0 + (wid >> 1) * 32 + j * 8 + 2 * t;
        m2a[j] = *(const float2*)&mup[pix];
        r2a[j] = *(const float2*)&rsp[pix];
    }
    #pragma unroll
    for (int i = 0; i < 4; i++) {
        #pragma unroll
        for (int half = 0; half < 2; half++) {
            int m = m0 + (wid & 1) * 64 + i * 16 + g + half * 8;
            if (m >= CC) continue;
            float bias = fb[m];
            float lwm = lnw[m], lbm = lnb[m];
            size_t base = (size_t)m * HWW;
            #pragma unroll
            for (int j = 0; j < 4; j++) {
                int pix = pix0 + (wid >> 1) * 32 + j * 8 + 2 * t;
                float2 xv = *(const float2*)&xb[base + pix];
                float xn0 = (xv.x - m2a[j].x) * r2a[j].x * lwm + lbm;
                float xn1 = (xv.y - m2a[j].y) * r2a[j].y * lwm + lbm;
                float2 v = make_float2(acc[i][j][half*2+0] + bias + xn0,
                                       acc[i][j][half*2+1] + bias + xn1);
                *(float2*)&out[(size_t)b * NPB + base + pix] = v;
            }
        }
    }
}

// ---------------- depthwise 3x3 for V only: bf16 in/out, 8 px/thread, transposed out ----------------
__global__ __launch_bounds__(256) void dw_v_kernel(const float* __restrict__ vw,
                                                   const float* __restrict__ vb) {
    __shared__ float tsm[128][17];
    int tid = threadIdx.x;
    int idx = blockIdx.x * 256 + tid;
    int w8 = (idx & 15) * 8;
    int h = (idx >> 4) & (HH - 1);
    int cg = idx >> 11;
    int c = cg % CC;
    const uint16_t* ip = g_tmp16 + 2 * (size_t)NTOT + (size_t)cg * HWW;
    const float* wp = vw + c * 9;
    float bv = vb[c];
    float a[8];
    #pragma unroll
    for (int k = 0; k < 8; k++) a[k] = bv;
    #pragma unroll
    for (int dy = 0; dy < 3; dy++) {
        int hh = h + dy - 1;
        if (hh < 0 || hh >= HH) continue;
        const uint16_t* row = ip + hh * WW + w8;
        uint4 rv = *(const uint4*)row;
        float m[8];
        m[0] = bf_lo(rv.x); m[1] = bf_hi(rv.x);
        m[2] = bf_lo(rv.y); m[3] = bf_hi(rv.y);
        m[4] = bf_lo(rv.z); m[5] = bf_hi(rv.z);
        m[6] = bf_lo(rv.w); m[7] = bf_hi(rv.w);
        float lf = (w8 > 0)   ? __uint_as_float(((uint32_t)row[-1]) << 16) : 0.f;
        float rt = (w8 < 120) ? __uint_as_float(((uint32_t)row[8])  << 16) : 0.f;
        float k0 = wp[dy*3], k1 = wp[dy*3+1], k2 = wp[dy*3+2];
        a[0] += k0*lf + k1*m[0] + k2*m[1];
        #pragma unroll
        for (int k = 1; k < 7; k++)
            a[k] += k0*m[k-1] + k1*m[k] + k2*m[k+1];
        a[7] += k0*m[6] + k1*m[7] + k2*rt;
    }
    int hl = tid >> 4;
    #pragma unroll
    for (int k = 0; k < 8; k++) tsm[w8 + k][hl] = a[k];
    __syncthreads();
    int wv = tid >> 1, half = tid & 1;
    int h0 = (blockIdx.x * 16) & (HH - 1);
    uint16_t* op = g_vt16 + (size_t)cg * HWW;
    float* r = &tsm[wv][half * 8];
    *(uint4*)&op[wv * WW + h0 + half * 8] =
        make_uint4(bf2(r[0], r[1]), bf2(r[2], r[3]), bf2(r[4], r[5]), bf2(r[6], r[7]));
}

// ---------------- fused dw(Q,K) + 48x48 Gram per (b, head, h-row) ----------------
#define GPITCH 129
__global__ __launch_bounds__(256) void dwqk_gram_kernel(const float* __restrict__ qw,
                                                        const float* __restrict__ kw,
                                                        const float* __restrict__ qb,
                                                        const float* __restrict__ kb) {
    __shared__ float Qs[SS * GPITCH];
    __shared__ float Ks[SS * GPITCH];
    int h = blockIdx.x;
    int bh = blockIdx.y;
    int b = bh >> 2, hd = bh & 3;
    int tid = threadIdx.x;

    #pragma unroll
    for (int slot = 0; slot < 2; slot++) {
        const float* wgt  = slot ? kw : qw;
        const float* bias = slot ? kb : qb;
        float* dst = slot ? Ks : Qs;
        const uint16_t* base = g_tmp16 + (size_t)slot * NTOT
                             + ((size_t)b * CC + hd * SS) * HWW;
        #pragma unroll
        for (int u = 0; u < 3; u++) {
            int unit = tid + u * 256;
            int ch = unit >> 4;
            int w8 = (unit & 15) * 8;
            int c = hd * SS + ch;
            const uint16_t* ip = base + (size_t)ch * HWW;
            const float* wp = wgt + c * 9;
            float bv = bias[c];
            float a[8];
            #pragma unroll
            for (int k = 0; k < 8; k++) a[k] = bv;
            #pragma unroll
            for (int dy = 0; dy < 3; dy++) {
                int hh = h + dy - 1;
                if (hh < 0 || hh >= HH) continue;
                const uint16_t* row = ip + hh * WW + w8;
                uint4 rv = *(const uint4*)row;
                float m[8];
                m[0] = bf_lo(rv.x); m[1] = bf_hi(rv.x);
                m[2] = bf_lo(rv.y); m[3] = bf_hi(rv.y);
                m[4] = bf_lo(rv.z); m[5] = bf_hi(rv.z);
                m[6] = bf_lo(rv.w); m[7] = bf_hi(rv.w);
                float lf = (w8 > 0)   ? __uint_as_float(((uint32_t)row[-1]) << 16) : 0.f;
                float rt = (w8 < 120) ? __uint_as_float(((uint32_t)row[8])  << 16) : 0.f;
                float k0 = wp[dy*3], k1 = wp[dy*3+1], k2 = wp[dy*3+2];
                a[0] += k0*lf + k1*m[0] + k2*m[1];
                #pragma unroll
                for (int k = 1; k < 7; k++)
                    a[k] += k0*m[k-1] + k1*m[k] + k2*m[k+1];
                a[7] += k0*m[6] + k1*m[7] + k2*rt;
            }
            #pragma unroll
            for (int k = 0; k < 8; k++) dst[ch * GPITCH + w8 + k] = a[k];
        }
    }
    __syncthreads();

    int tx = tid & 15, ty = tid >> 4;
    int s0 = ty * 3, q0 = tx * 3;
    float acc[3][3] = {};
    for (int p = 0; p < 128; p++) {
        float kv0 = Ks[(s0 + 0) * GPITCH + p];
        float kv1 = Ks[(s0 + 1) * GPITCH + p];
        float kv2 = Ks[(s0 + 2) * GPITCH + p];
        float qv0 = Qs[(q0 + 0) * GPITCH + p];
        float qv1 = Qs[(q0 + 1) * GPITCH + p];
        float qv2 = Qs[(q0 + 2) * GPITCH + p];
        acc[0][0] += kv0 * qv0; acc[0][1] += kv0 * qv1; acc[0][2] += kv0 * qv2;
        acc[1][0] += kv1 * qv0; acc[1][1] += kv1 * qv1; acc[1][2] += kv1 * qv2;
        acc[2][0] += kv2 * qv0; acc[2][1] += kv2 * qv1; acc[2][2] += kv2 * qv2;
    }
    float* ap = g_att + (size_t)bh * SS * SS;
    #pragma unroll
    for (int i = 0; i < 3; i++)
        #pragma unroll
        for (int j = 0; j < 3; j++)
            atomicAdd(&ap[(s0 + i) * SS + q0 + j], acc[i][j]);
}

// ---------------- softmax over q ----------------
__global__ void softmax_kernel(const float* __restrict__ alpha) {
    int bh = blockIdx.x;
    int s = threadIdx.x;
    float inva = 1.0f / alpha[0];
    float* row = g_att + ((size_t)bh * SS + s) * SS;
    float mx = -1e30f;
    for (int q = 0; q < SS; q++) mx = fmaxf(mx, row[q] * inva);
    float sum = 0.f;
    for (int q = 0; q < SS; q++) sum += expf(row[q] * inva - mx);
    float rs = 1.0f / sum;
    for (int q = 0; q < SS; q++) row[q] = expf(row[q] * inva - mx) * rs;
}

// ---------------- build fused matrix g_Gm[b][o][cv] ----------------
__global__ void buildG_kernel(const float* __restrict__ fw) {
    int b = blockIdx.x, cv = blockIdx.y;
    int hd = cv / SS, sl = cv % SS;
    __shared__ float arow[SS];
    int o = threadIdx.x;
    if (o < SS) arow[o] = g_att[(((size_t)b * NHEADS + hd) * SS + sl) * SS + o];
    __syncthreads();
    const float* fp = fw + (size_t)o * CC + hd * SS;
    float acc = 0.f;
    #pragma unroll
    for (int q = 0; q < SS; q++) acc += fp[q] * arow[q];
    g_Gm[((size_t)b * 256 + o) * CC + cv] = acc;
}

// ---------------- launch ----------------
extern "C" void kernel_launch(void* const* d_in, const int* in_sizes, int n_in,
                              void* d_out, int out_size) {
    const float* x      = (const float*)d_in[0];
    const float* ln_w   = (const float*)d_in[1];
    const float* ln_b   = (const float*)d_in[2];
    const float* q_pw_w = (const float*)d_in[3];
    const float* q_pw_b = (const float*)d_in[4];
    const float* q_dw_w = (const float*)d_in[5];
    const float* q_dw_b = (const float*)d_in[6];
    const float* k_pw_w = (const float*)d_in[7];
    const float* k_pw_b = (const float*)d_in[8];
    const float* k_dw_w = (const float*)d_in[9];
    const float* k_dw_b = (const float*)d_in[10];
    const float* v_pw_w = (const float*)d_in[11];
    const float* v_pw_b = (const float*)d_in[12];
    const float* v_dw_w = (const float*)d_in[13];
    const float* v_dw_b = (const float*)d_in[14];
    const float* f_w    = (const float*)d_in[15];
    const float* f_b    = (const float*)d_in[16];
    const float* alpha  = (const float*)d_in[17];
    float* out = (float*)d_out;

    cudaFuncSetAttribute(gemm_qkv_mma_kernel,   cudaFuncAttributeMaxDynamicSharedMemorySize, SMEM_QKV);
    cudaFuncSetAttribute(gemm_final_mma_kernel, cudaFuncAttributeMaxDynamicSharedMemorySize, SMEM_DB);

    prep_weights_kernel<<<(640 * CC + 255) / 256, 256>>>(q_pw_w, k_pw_w, v_pw_w,
                                                         q_pw_b, k_pw_b, v_pw_b);
    prep_frag_kernel<<<dim3(5, 6), 256>>>();
    zero_att_kernel<<<(BB * NHEADS * SS * SS + 255) / 256, 256>>>();
    ln_stats_kernel<<<BB * HWW / 128, 256>>>(x);
    gemm_qkv_mma_kernel<<<dim3(HWW / 128, BB), 256, SMEM_QKV>>>(x, ln_w, ln_b);
    dw_v_kernel<<<NTOT / 2048, 256>>>(v_dw_w, v_dw_b);
    dwqk_gram_kernel<<<dim3(HH, BB * NHEADS), 256>>>(q_dw_w, k_dw_w, q_dw_b, k_dw_b);
    softmax_kernel<<<BB * NHEADS, SS>>>(alpha);
    buildG_kernel<<<dim3(BB, CC), CC>>>(f_w);
    gemm_final_mma_kernel<<<dim3(2, HWW / 128, BB), 256, SMEM_DB>>>(x, ln_w, ln_b, f_b, out);
}

// round 16
// speedup vs baseline: 1.0577x; 1.0577x over previous
#include <cuda_runtime.h>
#include <math.h>
#include <stdint.h>

#define BB 8
#define CC 192
#define HH 128
#define WW 128
#define HWW (HH*WW)          // 16384
#define NHEADS 4
#define SS 48
#define NPB (CC*HWW)         // 3145728 per batch per tensor
#define NTOT (BB*NPB)

// ---------------- scratch ----------------
__device__ float g_mu[BB*HWW];          // per-pixel LN mean
__device__ float g_rs[BB*HWW];          // per-pixel LN rsqrt(var+eps)
__device__ uint16_t g_tmp16[3*NTOT];    // pw outputs Qp,Kp,Vp (bf16)
__device__ uint16_t g_vt16[NTOT];       // Vt (spatially transposed V after dw, bf16)
__device__ float g_att[BB*NHEADS*SS*SS];
__device__ float g_Gm[BB*256*CC];       // fused matrix per batch, [b][o(pad 256)][cv]
__device__ float g_w3[640*CC];          // stacked pw weights [m(pad 640)][k], fp32
__device__ uint32_t g_w3f[5*6*2048];    // pre-formatted bf16 A fragments
__device__ float g_b3[3*CC];

__device__ __forceinline__ uint32_t bf2(float lo, float hi) {
    uint32_t d;
    asm("cvt.rn.bf16x2.f32 %0, %1, %2;" : "=r"(d) : "f"(hi), "f"(lo));
    return d;
}
__device__ __forceinline__ float bf_lo(uint32_t u) { return __uint_as_float(u << 16); }
__device__ __forceinline__ float bf_hi(uint32_t u) { return __uint_as_float(u & 0xffff0000u); }

// ---------------- weight prep (+ att zeroing folded in) ----------------
__global__ void prep_weights_kernel(const float* __restrict__ qw, const float* __restrict__ kw,
                                    const float* __restrict__ vw, const float* __restrict__ qb,
                                    const float* __restrict__ kb, const float* __restrict__ vb) {
    int idx = blockIdx.x * 256 + threadIdx.x;
    if (idx < 640 * CC) {
        int m = idx / CC, k = idx % CC;
        float v = 0.0f;
        if (m < 576) {
            int slot = m / CC, o = m % CC;
            const float* w = (slot == 0) ? qw : (slot == 1) ? kw : vw;
            v = w[o * CC + k];
        }
        g_w3[idx] = v;
    }
    if (idx < 3 * CC) {
        int i = idx / CC, o = idx % CC;
        const float* bs = (i == 0) ? qb : (i == 1) ? kb : vb;
        g_b3[idx] = bs[o];
    }
    if (idx < BB * NHEADS * SS * SS) g_att[idx] = 0.0f;
}

// format g_w3 -> bf16 fragment layout. grid (5,6), 256 thr
__global__ void prep_frag_kernel() {
    int mb = blockIdx.x, kc = blockIdx.y;
    int tid = threadIdx.x;
    uint32_t* dst = g_w3f + (mb * 6 + kc) * 2048;
    #pragma unroll
    for (int u = 0; u < 2; u++) {
        int unit = tid + u * 256;
        int koq  = unit & 3;
        int g    = (unit >> 2) & 7;
        int ks   = (unit >> 5) & 1;
        int msub = unit >> 6;
        int r0 = mb * 128 + msub * 16 + g;
        int koff = koq * 4;
        int kk = kc * 32 + ks * 16 + koff;
        float4 v0 = *(const float4*)&g_w3[(size_t)r0 * CC + kk];
        float4 v1 = *(const float4*)&g_w3[(size_t)(r0 + 8) * CC + kk];
        int lane0 = g * 4 + ((koq * 2) & 3);
        int regbase = (koff >= 8) ? 2 : 0;
        uint32_t* blk = dst + (msub * 2 + ks) * 128;
        *(uint2*)(blk + lane0 * 4 + regbase)       = make_uint2(bf2(v0.x, v0.y), bf2(v1.x, v1.y));
        *(uint2*)(blk + (lane0 + 1) * 4 + regbase) = make_uint2(bf2(v0.z, v0.w), bf2(v1.z, v1.w));
    }
}

// ---------------- LN stats, 2 threads/pixel ----------------
__global__ __launch_bounds__(256) void ln_stats_kernel(const float* __restrict__ x) {
    __shared__ float ss[128], sq2[128];
    int tid = threadIdx.x;
    int p = blockIdx.x * 128 + (tid >> 1);
    int half = tid & 1;
    int b = p / HWW, sp = p % HWW;
    const float* xp = x + (size_t)b * NPB + sp + (size_t)(half * 96) * HWW;
    float s = 0.f, sq = 0.f;
    #pragma unroll 4
    for (int c = 0; c < 96; c++) {
        float v = xp[(size_t)c * HWW];
        s += v; sq += v * v;
    }
    if (half) { ss[tid >> 1] = s; sq2[tid >> 1] = sq; }
    __syncthreads();
    if (!half) {
        s += ss[tid >> 1]; sq += sq2[tid >> 1];
        float mu = s * (1.0f / CC);
        float var = sq * (1.0f / CC) - mu * mu;
        g_mu[p] = mu;
        g_rs[p] = rsqrtf(var + 1e-5f);
    }
}

// ============== bf16 mma.sync GEMM machinery (m16n8k16, double-buffered) ==============
#define A_BLK 132
#define B_BLK2 132
#define A_CH (16 * A_BLK)     // 2112 u32
#define B_CH (16 * B_BLK2)    // 2112 u32
#define BUF_U32 (A_CH + B_CH) // 4224
#define SMEM_DB (2 * BUF_U32 * 4)   // 33792 B
#define STAGE_PITCH 136
#define SMEM_QKV (128 * STAGE_PITCH * 2)   // 34816 B

#define MMA_BF16(acc, a0, a1, a2, a3, b0, b1) \
    asm volatile( \
        "mma.sync.aligned.m16n8k16.row.col.f32.bf16.bf16.f32 " \
        "{%0,%1,%2,%3}, {%4,%5,%6,%7}, {%8,%9}, {%0,%1,%2,%3};" \
        : "+f"((acc)[0]), "+f"((acc)[1]), "+f"((acc)[2]), "+f"((acc)[3]) \
        : "r"(a0), "r"(a1), "r"(a2), "r"(a3), "r"(b0), "r"(b1))

__device__ __forceinline__ void fill_A_pre(uint32_t* Ab, const uint32_t* src, int tid) {
    #pragma unroll
    for (int u = 0; u < 2; u++) {
        int f = tid + u * 256;
        int blk = f >> 5, lane = f & 31;
        uint4 v = ((const uint4*)src)[f];
        *(uint4*)(Ab + blk * A_BLK + lane * 4) = v;
    }
}

__device__ __forceinline__ void fill_A_f32(uint32_t* Ab, const float* Amat,
                                           int kbase, int arows, int tid) {
    #pragma unroll
    for (int u = 0; u < 2; u++) {
        int unit = tid + u * 256;
        int koq  = unit & 3;
        int g    = (unit >> 2) & 7;
        int ks   = (unit >> 5) & 1;
        int msub = unit >> 6;
        int r0 = msub * 16 + g;
        int koff = koq * 4;
        int kk = kbase + ks * 16 + koff;
        float4 v0 = make_float4(0.f,0.f,0.f,0.f), v1 = v0;
        if (r0 < arows)     v0 = *(const float4*)&Amat[(size_t)r0 * CC + kk];
        if (r0 + 8 < arows) v1 = *(const float4*)&Amat[(size_t)(r0 + 8) * CC + kk];
        int lane0 = g * 4 + ((koq * 2) & 3);
        int regbase = (koff >= 8) ? 2 : 0;
        uint32_t* blk = Ab + (msub * 2 + ks) * A_BLK;
        *(uint2*)(blk + lane0 * 4 + regbase)       = make_uint2(bf2(v0.x, v0.y), bf2(v1.x, v1.y));
        *(uint2*)(blk + (lane0 + 1) * 4 + regbase) = make_uint2(bf2(v0.z, v0.w), bf2(v1.z, v1.w));
    }
}

// ---- QKV B path: fp32 x + LN ----
__device__ __forceinline__ void load_B4(float4 v[4], const float* X,
                                        int kbase, int pix0, int tid) {
    int n4 = (tid & 31) * 4;
    int kp = (tid >> 5) & 3;
    int ks = tid >> 7;
    const float* base = X + (size_t)(kbase + ks * 16) * HWW + pix0 + n4;
    v[0] = *(const float4*)(base + (size_t)(2 * kp) * HWW);
    v[1] = *(const float4*)(base + (size_t)(2 * kp + 1) * HWW);
    v[2] = *(const float4*)(base + (size_t)(2 * kp + 8) * HWW);
    v[3] = *(const float4*)(base + (size_t)(2 * kp + 9) * HWW);
}

__device__ __forceinline__ void store_B_ln(uint32_t* Bb, const float4 v[4], int tid,
                                           const float4 mu4, const float4 r4,
                                           const float* __restrict__ lnw,
                                           const float* __restrict__ lnb, int kbase) {
    int n4 = (tid & 31) * 4;
    int kp = (tid >> 5) & 3;
    int ks = tid >> 7;
    int kk = kbase + ks * 16;
    float lw[4], lb[4];
    lw[0] = lnw[kk + 2*kp];     lb[0] = lnb[kk + 2*kp];
    lw[1] = lnw[kk + 2*kp + 1]; lb[1] = lnb[kk + 2*kp + 1];
    lw[2] = lnw[kk + 2*kp + 8]; lb[2] = lnb[kk + 2*kp + 8];
    lw[3] = lnw[kk + 2*kp + 9]; lb[3] = lnb[kk + 2*kp + 9];
    const float* e0 = (const float*)&v[0];
    const float* e1 = (const float*)&v[1];
    const float* e2 = (const float*)&v[2];
    const float* e3 = (const float*)&v[3];
    const float* mup = (const float*)&mu4;
    const float* rp  = (const float*)&r4;
    #pragma unroll
    for (int q = 0; q < 4; q++) {
        float sc = rp[q], mm = mup[q];
        float f0 = (e0[q] - mm) * sc * lw[0] + lb[0];
        float f1 = (e1[q] - mm) * sc * lw[1] + lb[1];
        float f2 = (e2[q] - mm) * sc * lw[2] + lb[2];
        float f3 = (e3[q] - mm) * sc * lw[3] + lb[3];
        int n = n4 + q;
        int npair = n >> 4, sub = (n >> 3) & 1, lane = (n & 7) * 4 + kp;
        *(uint2*)(Bb + (npair * 2 + ks) * B_BLK2 + lane * 4 + sub * 2) =
            make_uint2(bf2(f0, f1), bf2(f2, f3));
    }
}

// ---- final-GEMM B path: bf16 Vt, pure bit-shuffle ----
__device__ __forceinline__ void load_B4_bf(uint2 v[4], const uint16_t* X16,
                                           int kbase, int pix0, int tid) {
    int n4 = (tid & 31) * 4;
    int kp = (tid >> 5) & 3;
    int ks = tid >> 7;
    const uint16_t* base = X16 + (size_t)(kbase + ks * 16) * HWW + pix0 + n4;
    v[0] = *(const uint2*)(base + (size_t)(2 * kp) * HWW);
    v[1] = *(const uint2*)(base + (size_t)(2 * kp + 1) * HWW);
    v[2] = *(const uint2*)(base + (size_t)(2 * kp + 8) * HWW);
    v[3] = *(const uint2*)(base + (size_t)(2 * kp + 9) * HWW);
}
__device__ __forceinline__ uint32_t bfsel(const uint2 r, int q) {
    uint32_t w = (q < 2) ? r.x : r.y;
    return (q & 1) ? (w >> 16) : (w & 0xffffu);
}
__device__ __forceinline__ void store_B_bf(uint32_t* Bb, const uint2 v[4], int tid) {
    int n4 = (tid & 31) * 4;
    int kp = (tid >> 5) & 3;
    int ks = tid >> 7;
    #pragma unroll
    for (int q = 0; q < 4; q++) {
        uint32_t lo = bfsel(v[0], q) | (bfsel(v[1], q) << 16);
        uint32_t hi = bfsel(v[2], q) | (bfsel(v[3], q) << 16);
        int n = n4 + q;
        int npair = n >> 4, sub = (n >> 3) & 1, lane = (n & 7) * 4 + kp;
        *(uint2*)(Bb + (npair * 2 + ks) * B_BLK2 + lane * 4 + sub * 2) = make_uint2(lo, hi);
    }
}

__device__ __forceinline__ void mma_chunk(float acc[4][4][4], const uint32_t* Ab,
                                          const uint32_t* Bb, int wm, int wnp, int lane) {
    #pragma unroll
    for (int ks = 0; ks < 2; ks++) {
        uint32_t ah[4][4], bh[4][2];
        #pragma unroll
        for (int i = 0; i < 4; i++) {
            uint4 t = *(const uint4*)(Ab + ((wm + i) * 2 + ks) * A_BLK + lane * 4);
            ah[i][0] = t.x; ah[i][1] = t.y; ah[i][2] = t.z; ah[i][3] = t.w;
        }
        #pragma unroll
        for (int jp = 0; jp < 2; jp++) {
            uint4 t = *(const uint4*)(Bb + ((wnp + jp) * 2 + ks) * B_BLK2 + lane * 4);
            bh[jp*2][0] = t.x; bh[jp*2][1] = t.y;
            bh[jp*2+1][0] = t.z; bh[jp*2+1][1] = t.w;
        }
        #pragma unroll
        for (int i = 0; i < 4; i++)
            #pragma unroll
            for (int j = 0; j < 4; j++)
                MMA_BF16(acc[i][j], ah[i][0], ah[i][1], ah[i][2], ah[i][3], bh[j][0], bh[j][1]);
    }
}

// ---------------- QKV pointwise GEMM (R14 structure: per-CTA m-block, pipelined) ----------------
__global__ __launch_bounds__(256, 2) void gemm_qkv_mma_kernel(const float* __restrict__ x,
                                                              const float* __restrict__ lnw,
                                                              const float* __restrict__ lnb) {
    extern __shared__ uint32_t usm[];
    const int tid = threadIdx.x;
    const int wid = tid >> 5, lane = tid & 31;
    const int mb = blockIdx.x;
    const int pix0 = blockIdx.y * 128;
    const int b = blockIdx.z;
    const int m0 = mb * 128;
    const int wm = (wid & 1) * 4;
    const int wnp = (wid >> 1) * 2;
    const float* X = x + (size_t)b * NPB;
    const uint32_t* Asrc = g_w3f + mb * 6 * 2048;

    float4 mu4, r4;
    {
        int n4 = (tid & 31) * 4;
        mu4 = *(const float4*)&g_mu[(size_t)b * HWW + pix0 + n4];
        r4  = *(const float4*)&g_rs[(size_t)b * HWW + pix0 + n4];
    }
    float acc[4][4][4] = {};
    float4 breg[4];
    load_B4(breg, X, 0, pix0, tid);
    fill_A_pre(usm, Asrc, tid);
    store_B_ln(usm + A_CH, breg, tid, mu4, r4, lnw, lnb, 0);
    __syncthreads();
    #pragma unroll 1
    for (int kc = 0; kc < 6; kc++) {
        uint32_t* cur = usm + (kc & 1) * BUF_U32;
        uint32_t* nxt = usm + ((kc + 1) & 1) * BUF_U32;
        if (kc < 5) load_B4(breg, X, (kc + 1) * 32, pix0, tid);
        mma_chunk(acc, cur, cur + A_CH, wm, wnp, lane);
        if (kc < 5) {
            fill_A_pre(nxt, Asrc + (kc + 1) * 2048, tid);
            store_B_ln(nxt + A_CH, breg, tid, mu4, r4, lnw, lnb, (kc + 1) * 32);
        }
        __syncthreads();
    }

    uint16_t* stage = (uint16_t*)usm;
    int g = lane >> 2, t = lane & 3;
    #pragma unroll
    for (int i = 0; i < 4; i++) {
        #pragma unroll
        for (int half = 0; half < 2; half++) {
            int mrow = (wid & 1) * 64 + i * 16 + g + half * 8;
            int m = m0 + mrow;
            float bias = (m < 576) ? g_b3[m] : 0.f;
            #pragma unroll
            for (int j = 0; j < 4; j++) {
                int px = (wid >> 1) * 32 + j * 8 + 2 * t;
                *(uint32_t*)&stage[mrow * STAGE_PITCH + px] =
                    bf2(acc[i][j][half*2+0] + bias, acc[i][j][half*2+1] + bias);
            }
        }
    }
    __syncthreads();
    #pragma unroll
    for (int u = 0; u < 8; u++) {
        int f = tid + u * 256;
        int mrow = f >> 4, chunk = f & 15;
        int m = m0 + mrow;
        if (m >= 576) continue;
        int slot = m / CC, o = m - slot * CC;
        uint4 v = *(const uint4*)&stage[mrow * STAGE_PITCH + chunk * 8];
        *(uint4*)&g_tmp16[(size_t)slot * NTOT + (size_t)b * NPB + (size_t)o * HWW + pix0 + chunk * 8] = v;
    }
}

// ---------------- final GEMM: y = G[b] @ Vt(bf16) + f_b + xn(recomputed) ----------------
__global__ __launch_bounds__(256, 2) void gemm_final_mma_kernel(const float* __restrict__ x,
                                                                const float* __restrict__ lnw,
                                                                const float* __restrict__ lnb,
                                                                const float* __restrict__ fb,
                                                                float* __restrict__ out) {
    extern __shared__ uint32_t usm[];
    const int tid = threadIdx.x;
    const int wid = tid >> 5, lane = tid & 31;
    const int m0 = blockIdx.x * 128;
    const int pix0 = blockIdx.y * 128;
    const int b = blockIdx.z;
    const int arows = (m0 == 0) ? 128 : (CC - 128);
    const int wm = (wid & 1) * 4;
    const int wnp = (wid >> 1) * 2;
    const float* Amat = g_Gm + ((size_t)b * 256 + m0) * CC;
    const uint16_t* X16 = g_vt16 + (size_t)b * NPB;

    float acc[4][4][4] = {};
    uint2 breg[4];
    load_B4_bf(breg, X16, 0, pix0, tid);
    fill_A_f32(usm, Amat, 0, arows, tid);
    store_B_bf(usm + A_CH, breg, tid);
    __syncthreads();
    #pragma unroll 1
    for (int kc = 0; kc < 6; kc++) {
        uint32_t* cur = usm + (kc & 1) * BUF_U32;
        uint32_t* nxt = usm + ((kc + 1) & 1) * BUF_U32;
        if (kc < 5) load_B4_bf(breg, X16, (kc + 1) * 32, pix0, tid);
        mma_chunk(acc, cur, cur + A_CH, wm, wnp, lane);
        if (kc < 5) {
            fill_A_f32(nxt, Amat, (kc + 1) * 32, arows, tid);
            store_B_bf(nxt + A_CH, breg, tid);
        }
        __syncthreads();
    }

    int g = lane >> 2, t = lane & 3;
    const float* xb = x + (size_t)b * NPB;
    const float* mup = g_mu + (size_t)b * HWW;
    const float* rsp = g_rs + (size_t)b * HWW;
    float2 m2a[4], r2a[4];
    #pragma unroll
    for (int j = 0; j < 4; j++) {
        int pix = pix0 + (wid >> 1) * 32 + j * 8 + 2 * t;
        m2a[j] = *(const float2*)&mup[pix];
        r2a[j] = *(const float2*)&rsp[pix];
    }
    #pragma unroll
    for (int i = 0; i < 4; i++) {
        #pragma unroll
        for (int half = 0; half < 2; half++) {
            int m = m0 + (wid & 1) * 64 + i * 16 + g + half * 8;
            if (m >= CC) continue;
            float bias = fb[m];
            float lwm = lnw[m], lbm = lnb[m];
            size_t base = (size_t)m * HWW;
            #pragma unroll
            for (int j = 0; j < 4; j++) {
                int pix = pix0 + (wid >> 1) * 32 + j * 8 + 2 * t;
                float2 xv = *(const float2*)&xb[base + pix];
                float xn0 = (xv.x - m2a[j].x) * r2a[j].x * lwm + lbm;
                float xn1 = (xv.y - m2a[j].y) * r2a[j].y * lwm + lbm;
                float2 v = make_float2(acc[i][j][half*2+0] + bias + xn0,
                                       acc[i][j][half*2+1] + bias + xn1);
                *(float2*)&out[(size_t)b * NPB + base + pix] = v;
            }
        }
    }
}

// ---------------- depthwise 3x3 for V only: bf16 in/out, 8 px/thread, transposed out ----------------
__global__ __launch_bounds__(256) void dw_v_kernel(const float* __restrict__ vw,
                                                   const float* __restrict__ vb) {
    __shared__ float tsm[128][17];
    int tid = threadIdx.x;
    int idx = blockIdx.x * 256 + tid;
    int w8 = (idx & 15) * 8;
    int h = (idx >> 4) & (HH - 1);
    int cg = idx >> 11;
    int c = cg % CC;
    const uint16_t* ip = g_tmp16 + 2 * (size_t)NTOT + (size_t)cg * HWW;
    const float* wp = vw + c * 9;
    float bv = vb[c];
    float a[8];
    #pragma unroll
    for (int k = 0; k < 8; k++) a[k] = bv;
    #pragma unroll
    for (int dy = 0; dy < 3; dy++) {
        int hh = h + dy - 1;
        if (hh < 0 || hh >= HH) continue;
        const uint16_t* row = ip + hh * WW + w8;
        uint4 rv = *(const uint4*)row;
        float m[8];
        m[0] = bf_lo(rv.x); m[1] = bf_hi(rv.x);
        m[2] = bf_lo(rv.y); m[3] = bf_hi(rv.y);
        m[4] = bf_lo(rv.z); m[5] = bf_hi(rv.z);
        m[6] = bf_lo(rv.w); m[7] = bf_hi(rv.w);
        float lf = (w8 > 0)   ? __uint_as_float(((uint32_t)row[-1]) << 16) : 0.f;
        float rt = (w8 < 120) ? __uint_as_float(((uint32_t)row[8])  << 16) : 0.f;
        float k0 = wp[dy*3], k1 = wp[dy*3+1], k2 = wp[dy*3+2];
        a[0] += k0*lf + k1*m[0] + k2*m[1];
        #pragma unroll
        for (int k = 1; k < 7; k++)
            a[k] += k0*m[k-1] + k1*m[k] + k2*m[k+1];
        a[7] += k0*m[6] + k1*m[7] + k2*rt;
    }
    int hl = tid >> 4;
    #pragma unroll
    for (int k = 0; k < 8; k++) tsm[w8 + k][hl] = a[k];
    __syncthreads();
    int wv = tid >> 1, half = tid & 1;
    int h0 = (blockIdx.x * 16) & (HH - 1);
    uint16_t* op = g_vt16 + (size_t)cg * HWW;
    float* r = &tsm[wv][half * 8];
    *(uint4*)&op[wv * WW + h0 + half * 8] =
        make_uint4(bf2(r[0], r[1]), bf2(r[2], r[3]), bf2(r[4], r[5]), bf2(r[6], r[7]));
}

// ---------------- fused dw(Q,K) + 48x48 Gram per (b, head, h-row) ----------------
#define GPITCH 129
__global__ __launch_bounds__(256) void dwqk_gram_kernel(const float* __restrict__ qw,
                                                        const float* __restrict__ kw,
                                                        const float* __restrict__ qb,
                                                        const float* __restrict__ kb) {
    __shared__ float Qs[SS * GPITCH];
    __shared__ float Ks[SS * GPITCH];
    int h = blockIdx.x;
    int bh = blockIdx.y;
    int b = bh >> 2, hd = bh & 3;
    int tid = threadIdx.x;

    #pragma unroll
    for (int slot = 0; slot < 2; slot++) {
        const float* wgt  = slot ? kw : qw;
        const float* bias = slot ? kb : qb;
        float* dst = slot ? Ks : Qs;
        const uint16_t* base = g_tmp16 + (size_t)slot * NTOT
                             + ((size_t)b * CC + hd * SS) * HWW;
        #pragma unroll
        for (int u = 0; u < 3; u++) {
            int unit = tid + u * 256;
            int ch = unit >> 4;
            int w8 = (unit & 15) * 8;
            int c = hd * SS + ch;
            const uint16_t* ip = base + (size_t)ch * HWW;
            const float* wp = wgt + c * 9;
            float bv = bias[c];
            float a[8];
            #pragma unroll
            for (int k = 0; k < 8; k++) a[k] = bv;
            #pragma unroll
            for (int dy = 0; dy < 3; dy++) {
                int hh = h + dy - 1;
                if (hh < 0 || hh >= HH) continue;
                const uint16_t* row = ip + hh * WW + w8;
                uint4 rv = *(const uint4*)row;
                float m[8];
                m[0] = bf_lo(rv.x); m[1] = bf_hi(rv.x);
                m[2] = bf_lo(rv.y); m[3] = bf_hi(rv.y);
                m[4] = bf_lo(rv.z); m[5] = bf_hi(rv.z);
                m[6] = bf_lo(rv.w); m[7] = bf_hi(rv.w);
                float lf = (w8 > 0)   ? __uint_as_float(((uint32_t)row[-1]) << 16) : 0.f;
                float rt = (w8 < 120) ? __uint_as_float(((uint32_t)row[8])  << 16) : 0.f;
                float k0 = wp[dy*3], k1 = wp[dy*3+1], k2 = wp[dy*3+2];
                a[0] += k0*lf + k1*m[0] + k2*m[1];
                #pragma unroll
                for (int k = 1; k < 7; k++)
                    a[k] += k0*m[k-1] + k1*m[k] + k2*m[k+1];
                a[7] += k0*m[6] + k1*m[7] + k2*rt;
            }
            #pragma unroll
            for (int k = 0; k < 8; k++) dst[ch * GPITCH + w8 + k] = a[k];
        }
    }
    __syncthreads();

    int tx = tid & 15, ty = tid >> 4;
    int s0 = ty * 3, q0 = tx * 3;
    float acc[3][3] = {};
    for (int p = 0; p < 128; p++) {
        float kv0 = Ks[(s0 + 0) * GPITCH + p];
        float kv1 = Ks[(s0 + 1) * GPITCH + p];
        float kv2 = Ks[(s0 + 2) * GPITCH + p];
        float qv0 = Qs[(q0 + 0) * GPITCH + p];
        float qv1 = Qs[(q0 + 1) * GPITCH + p];
        float qv2 = Qs[(q0 + 2) * GPITCH + p];
        acc[0][0] += kv0 * qv0; acc[0][1] += kv0 * qv1; acc[0][2] += kv0 * qv2;
        acc[1][0] += kv1 * qv0; acc[1][1] += kv1 * qv1; acc[1][2] += kv1 * qv2;
        acc[2][0] += kv2 * qv0; acc[2][1] += kv2 * qv1; acc[2][2] += kv2 * qv2;
    }
    float* ap = g_att + (size_t)bh * SS * SS;
    #pragma unroll
    for (int i = 0; i < 3; i++)
        #pragma unroll
        for (int j = 0; j < 3; j++)
            atomicAdd(&ap[(s0 + i) * SS + q0 + j], acc[i][j]);
}

// ---------------- softmax over q ----------------
__global__ void softmax_kernel(const float* __restrict__ alpha) {
    int bh = blockIdx.x;
    int s = threadIdx.x;
    float inva = 1.0f / alpha[0];
    float* row = g_att + ((size_t)bh * SS + s) * SS;
    float mx = -1e30f;
    for (int q = 0; q < SS; q++) mx = fmaxf(mx, row[q] * inva);
    float sum = 0.f;
    for (int q = 0; q < SS; q++) sum += expf(row[q] * inva - mx);
    float rs = 1.0f / sum;
    for (int q = 0; q < SS; q++) row[q] = expf(row[q] * inva - mx) * rs;
}

// ---------------- build fused matrix g_Gm[b][o][cv] ----------------
__global__ void buildG_kernel(const float* __restrict__ fw) {
    int b = blockIdx.x, cv = blockIdx.y;
    int hd = cv / SS, sl = cv % SS;
    __shared__ float arow[SS];
    int o = threadIdx.x;
    if (o < SS) arow[o] = g_att[(((size_t)b * NHEADS + hd) * SS + sl) * SS + o];
    __syncthreads();
    const float* fp = fw + (size_t)o * CC + hd * SS;
    float acc = 0.f;
    #pragma unroll
    for (int q = 0; q < SS; q++) acc += fp[q] * arow[q];
    g_Gm[((size_t)b * 256 + o) * CC + cv] = acc;
}

// ---------------- launch ----------------
extern "C" void kernel_launch(void* const* d_in, const int* in_sizes, int n_in,
                              void* d_out, int out_size) {
    const float* x      = (const float*)d_in[0];
    const float* ln_w   = (const float*)d_in[1];
    const float* ln_b   = (const float*)d_in[2];
    const float* q_pw_w = (const float*)d_in[3];
    const float* q_pw_b = (const float*)d_in[4];
    const float* q_dw_w = (const float*)d_in[5];
    const float* q_dw_b = (const float*)d_in[6];
    const float* k_pw_w = (const float*)d_in[7];
    const float* k_pw_b = (const float*)d_in[8];
    const float* k_dw_w = (const float*)d_in[9];
    const float* k_dw_b = (const float*)d_in[10];
    const float* v_pw_w = (const float*)d_in[11];
    const float* v_pw_b = (const float*)d_in[12];
    const float* v_dw_w = (const float*)d_in[13];
    const float* v_dw_b = (const float*)d_in[14];
    const float* f_w    = (const float*)d_in[15];
    const float* f_b    = (const float*)d_in[16];
    const float* alpha  = (const float*)d_in[17];
    float* out = (float*)d_out;

    cudaFuncSetAttribute(gemm_qkv_mma_kernel,   cudaFuncAttributeMaxDynamicSharedMemorySize, SMEM_QKV);
    cudaFuncSetAttribute(gemm_final_mma_kernel, cudaFuncAttributeMaxDynamicSharedMemorySize, SMEM_DB);

    prep_weights_kernel<<<(640 * CC + 255) / 256, 256>>>(q_pw_w, k_pw_w, v_pw_w,
                                                         q_pw_b, k_pw_b, v_pw_b);
    prep_frag_kernel<<<dim3(5, 6), 256>>>();
    ln_stats_kernel<<<BB * HWW / 128, 256>>>(x);
    gemm_qkv_mma_kernel<<<dim3(5, HWW / 128, BB), 256, SMEM_QKV>>>(x, ln_w, ln_b);
    dw_v_kernel<<<NTOT / 2048, 256>>>(v_dw_w, v_dw_b);
    dwqk_gram_kernel<<<dim3(HH, BB * NHEADS), 256>>>(q_dw_w, k_dw_w, q_dw_b, k_dw_b);
    softmax_kernel<<<BB * NHEADS, SS>>>(alpha);
    buildG_kernel<<<dim3(BB, CC), CC>>>(f_w);
    gemm_final_mma_kernel<<<dim3(2, HWW / 128, BB), 256, SMEM_DB>>>(x, ln_w, ln_b, f_b, out);
}